// round 11
// baseline (speedup 1.0000x reference)
#include <cuda_runtime.h>
#include <cuda_bf16.h>
#include <cstdint>

// Problem constants (BuseE): N_ENT=200000, N_REL=500, DIM=64, B=1024, NC=1024
#define N_ENT 200000
#define BQ    1024
#define NC    1024
#define MARGIN 9.0f
#define EPS 1e-15f

#define TAIL_BLOCKS (N_ENT / 64)   // 3125 (64 rows / 256-thr block, 4 lanes/row)
#define HEAD_BLOCKS (BQ / 8)       // 128

// ---------------- device scratch (allocation-free) ----------------
// per-entity 128B line: [0,64) = 64 x int8 dims; [64,80) = float4 meta
// meta = { t2, log(max(1-t2,eps)), bias_tail, sc }
__device__ uint4 g_row[N_ENT * 8];          // 25.6 MB
// per-b quantized head: 64 x int8 = 16 words
__device__ unsigned g_headq[BQ * 16];
// per-b: { A, sig, hh, 2*sh/(127*127) }
__device__ float4 g_rowc[BQ];

// ---------------- fast math helpers -------------------------------
__device__ __forceinline__ float tanh_approx(float x) {
    float r;
    asm("tanh.approx.f32 %0, %1;" : "=f"(r) : "f"(x));
    return r;
}

__device__ __forceinline__ int redux_add(int v, unsigned mask) {
    int r;
    asm("redux.sync.add.s32 %0, %1, %2;" : "=r"(r) : "r"(v), "r"(mask));
    return r;
}

__device__ __forceinline__ float wsum32(float v) {
    #pragma unroll
    for (int m = 16; m; m >>= 1) v += __shfl_xor_sync(0xffffffffu, v, m);
    return v;
}
__device__ __forceinline__ float wmax32(float v) {
    #pragma unroll
    for (int m = 16; m; m >>= 1)
        v = fmaxf(v, __shfl_xor_sync(0xffffffffu, v, m));
    return v;
}

// ---------------- head transform primitives (warp-per-row) --------
__device__ __forceinline__ float2 expmap0_w(float2 v) {
    float n2   = wsum32(v.x * v.x + v.y * v.y);
    float rinv = rsqrtf(fmaxf(n2, 1e-36f));
    float un   = fmaxf(n2 * rinv, EPS);
    float f    = tanh_approx(un) * rinv;
    return make_float2(f * v.x, f * v.y);
}

__device__ __forceinline__ float2 mobius_w(float2 x, float2 y) {
    float x2 = wsum32(x.x * x.x + x.y * x.y);
    float y2 = wsum32(y.x * y.x + y.y * y.y);
    float xy = wsum32(x.x * y.x + x.y * y.y);
    float a   = 1.f + 2.f * xy + y2;
    float bq  = 1.f - x2;
    float inv = 1.f / fmaxf(1.f + 2.f * xy + x2 * y2, EPS);
    return make_float2((a * x.x + bq * y.x) * inv,
                       (a * x.y + bq * y.y) * inv);
}

__device__ __forceinline__ unsigned pack4(float a, float b, float c, float d,
                                          float fi) {
    int q0 = __float2int_rn(a * fi);
    int q1 = __float2int_rn(b * fi);
    int q2 = __float2int_rn(c * fi);
    int q3 = __float2int_rn(d * fi);
    return (q0 & 0xFF) | ((q1 & 0xFF) << 8) | ((q2 & 0xFF) << 16)
         | ((unsigned)(q3 & 0xFF) << 24);
}

// ---------------- fused prep kernel -------------------------------
__global__ void __launch_bounds__(256) prep_kernel(
    const int* __restrict__ u_idx, const int* __restrict__ r_idx,
    const float* __restrict__ emb, const float* __restrict__ rel_diag,
    const float* __restrict__ rb1, const float* __restrict__ rb2,
    const float* __restrict__ bias_head, const float* __restrict__ bias_tail,
    const float* __restrict__ sigma)
{
    if (blockIdx.x < TAIL_BLOCKS) {
        // ---- tail path: 4 lanes per entity row (64 rows / block) ----
        int row = blockIdx.x * 64 + (threadIdx.x >> 2);
        int s   = threadIdx.x & 3;        // lane covers dims [s*16, s*16+16)

        const float4* e4 = reinterpret_cast<const float4*>(emb) + (size_t)row * 16;
        float4 a = e4[s * 4 + 0];
        float4 b = e4[s * 4 + 1];
        float4 c = e4[s * 4 + 2];
        float4 d = e4[s * 4 + 3];

        float p = a.x*a.x + a.y*a.y + a.z*a.z + a.w*a.w
                + b.x*b.x + b.y*b.y + b.z*b.z + b.w*b.w
                + c.x*c.x + c.y*c.y + c.z*c.z + c.w*c.w
                + d.x*d.x + d.y*d.y + d.z*d.z + d.w*d.w;
        float am = fmaxf(fmaxf(fmaxf(fabsf(a.x), fabsf(a.y)),
                               fmaxf(fabsf(a.z), fabsf(a.w))),
                   fmaxf(fmaxf(fabsf(b.x), fabsf(b.y)),
                         fmaxf(fabsf(b.z), fabsf(b.w))));
        am = fmaxf(am, fmaxf(fmaxf(fabsf(c.x), fabsf(c.y)),
                             fmaxf(fabsf(c.z), fabsf(c.w))));
        am = fmaxf(am, fmaxf(fmaxf(fabsf(d.x), fabsf(d.y)),
                             fmaxf(fabsf(d.z), fabsf(d.w))));
        #pragma unroll
        for (int m = 2; m; m >>= 1) {
            p  += __shfl_xor_sync(0xffffffffu, p, m);
            am  = fmaxf(am, __shfl_xor_sync(0xffffffffu, am, m));
        }

        float rinv = rsqrtf(fmaxf(p, 1e-36f));
        float un   = fmaxf(p * rinv, EPS);
        float f    = tanh_approx(un) * rinv;   // tail = f * u
        float sc   = f * am;                   // max |tail_i|
        float fi   = 127.f * f / fmaxf(sc, 1e-30f);

        uint4 o;
        o.x = pack4(a.x, a.y, a.z, a.w, fi);
        o.y = pack4(b.x, b.y, b.z, b.w, fi);
        o.z = pack4(c.x, c.y, c.z, c.w, fi);
        o.w = pack4(d.x, d.y, d.z, d.w, fi);
        g_row[(size_t)row * 8 + s] = o;

        if (s == 0) {
            float t  = tanh_approx(un);
            float t2 = t * t;
            float4 meta = make_float4(t2, __logf(fmaxf(1.f - t2, EPS)),
                                      bias_tail[row], sc);
            g_row[(size_t)row * 8 + 4] = *reinterpret_cast<uint4*>(&meta);
        }
    } else {
        // ---- head path: 1 warp per b-row (8 rows / block) ----
        int b    = (blockIdx.x - TAIL_BLOCKS) * 8 + (threadIdx.x >> 5);
        int lane = threadIdx.x & 31;
        int u = u_idx[b];
        int r = r_idx[b];

        float2 h  = expmap0_w(reinterpret_cast<const float2*>(emb + (size_t)u * 64)[lane]);
        float2 y1 = expmap0_w(reinterpret_cast<const float2*>(rb1 + (size_t)r * 64)[lane]);
        h = mobius_w(h, y1);

        float2 g  = reinterpret_cast<const float2*>(rel_diag + (size_t)r * 64)[lane];
        float gri = rsqrtf(fmaxf(g.x * g.x + g.y * g.y, 1e-36f));
        float gx = g.x * gri, gy = g.y * gri;
        float2 rot = make_float2(gx * h.x - gy * h.y, gy * h.x + gx * h.y);

        float2 y2 = expmap0_w(reinterpret_cast<const float2*>(rb2 + (size_t)r * 64)[lane]);
        h = mobius_w(rot, y2);

        float hh = wsum32(h.x * h.x + h.y * h.y);
        float sh = fmaxf(wmax32(fmaxf(fabsf(h.x), fabsf(h.y))), 1e-30f);
        float inv = 127.f / sh;

        int q0 = __float2int_rn(h.x * inv);
        int q1 = __float2int_rn(h.y * inv);
        unsigned pk = (q0 & 0xFF) | ((q1 & 0xFF) << 8);
        unsigned other = __shfl_xor_sync(0xffffffffu, pk, 1);
        if ((lane & 1) == 0)
            g_headq[b * 16 + (lane >> 1)] = (pk & 0xFFFFu) | (other << 16);

        if (lane == 0) {
            float sg = 1.f / (1.f + __expf(-sigma[r]));
            float A  = MARGIN + bias_head[u]
                     + (1.f - sg) * __logf(fmaxf(1.f - hh, EPS));
            g_rowc[b] = make_float4(A, sg, hh, 2.f * sh / 16129.f);
        }
    }
}

// ---------------- scoring (hot loop) ------------------------------
// Warp owns 32 candidates in 2 flat-pipelined bursts of 16.
// 8-lane group g owns candidates [cbase+4g, +4) and [cbase+16+4g, +4):
// idx arrives as int4 LDG.128, results leave as float4 STG.128.
// Lanes s<4 hold int8 dims, lane s==4 holds float4 meta — one 128B line
// per element. DP4A dot, redux.sync group reduce, epilogue on lane s==4.
__global__ void __launch_bounds__(128) score_kernel(
    const int* __restrict__ v_idx, float* __restrict__ out)
{
    int w    = threadIdx.x >> 5;
    int gw   = blockIdx.x * 4 + w;       // global warp id
    int b    = gw >> 5;                  // b-row (32 warps per row)
    int seg  = gw & 31;                  // 32-candidate segment
    int lane = threadIdx.x & 31;
    int g    = lane >> 3;                // group 0..3
    int s    = lane & 7;                 // slot in group
    unsigned gmask = 0xFFu << (g * 8);

    int cbase = seg * 32;
    const int4* vrow4 = reinterpret_cast<const int4*>(v_idx + b * NC);
    float*      orow  = out + b * NC;

    // ---- flat idx loads for both bursts ----
    int4 V0 = __ldg(vrow4 + seg * 8 + g);        // cands cbase+4g..+3
    int4 V1 = __ldg(vrow4 + seg * 8 + 4 + g);    // cands cbase+16+4g..+3

    uint4 hq = reinterpret_cast<const uint4*>(g_headq)[b * 4 + (s & 3)];
    float4 rc = g_rowc[b];               // {A, sig, hh, 2*sh/127^2}

    // ---- flat payload gathers (32-bit offsets, 8 lines in flight) ----
    const char* base = reinterpret_cast<const char*>(g_row);
    unsigned so = (unsigned)s * 16u;
    int v0[4] = { V0.x, V0.y, V0.z, V0.w };
    int v1[4] = { V1.x, V1.y, V1.z, V1.w };

    uint4 p0[4], p1[4];
    #pragma unroll
    for (int j = 0; j < 4; j++) {
        p0[j] = make_uint4(0u, 0u, 0u, 0u);
        p1[j] = make_uint4(0u, 0u, 0u, 0u);
        if (s < 5) {
            p0[j] = *reinterpret_cast<const uint4*>(
                        base + ((unsigned)v0[j] * 128u + so));
            p1[j] = *reinterpret_cast<const uint4*>(
                        base + ((unsigned)v1[j] * 128u + so));
        }
    }

    // ---- integer dots ----
    int I0[4], I1[4];
    #pragma unroll
    for (int j = 0; j < 4; j++) {
        int a0 = 0, a1 = 0;
        if (s < 4) {
            a0 = __dp4a((int)p0[j].x, (int)hq.x, a0);
            a0 = __dp4a((int)p0[j].y, (int)hq.y, a0);
            a0 = __dp4a((int)p0[j].z, (int)hq.z, a0);
            a0 = __dp4a((int)p0[j].w, (int)hq.w, a0);
            a1 = __dp4a((int)p1[j].x, (int)hq.x, a1);
            a1 = __dp4a((int)p1[j].y, (int)hq.y, a1);
            a1 = __dp4a((int)p1[j].z, (int)hq.z, a1);
            a1 = __dp4a((int)p1[j].w, (int)hq.w, a1);
        }
        I0[j] = a0;
        I1[j] = a1;
    }

    // ---- one redux per element (group-scoped sum, lands on all lanes) --
    #pragma unroll
    for (int j = 0; j < 4; j++) {
        I0[j] = redux_add(I0[j], gmask);
        I1[j] = redux_add(I1[j], gmask);
    }

    // ---- epilogue + two STG.128 on meta lane ----
    if (s == 4) {
        float r0[4], r1[4];
        #pragma unroll
        for (int j = 0; j < 4; j++) {
            float4 m0 = *reinterpret_cast<float4*>(&p0[j]); // {t2,l,bias,sc}
            float4 m1 = *reinterpret_cast<float4*>(&p1[j]);
            float n0 = fmaxf(rc.z + m0.x - rc.w * m0.w * (float)I0[j], EPS);
            float n1 = fmaxf(rc.z + m1.x - rc.w * m1.w * (float)I1[j], EPS);
            r0[j] = rc.x + fmaf(rc.y, m0.y, m0.z) - __logf(n0);
            r1[j] = rc.x + fmaf(rc.y, m1.y, m1.z) - __logf(n1);
        }
        *reinterpret_cast<float4*>(orow + cbase + 4 * g) =
            make_float4(r0[0], r0[1], r0[2], r0[3]);
        *reinterpret_cast<float4*>(orow + cbase + 16 + 4 * g) =
            make_float4(r1[0], r1[1], r1[2], r1[3]);
    }
}

// ---------------- launch ------------------------------------------
extern "C" void kernel_launch(void* const* d_in, const int* in_sizes, int n_in,
                              void* d_out, int out_size)
{
    const int*   u_idx     = (const int*)  d_in[0];
    const int*   r_idx     = (const int*)  d_in[1];
    const int*   v_idx     = (const int*)  d_in[2];
    const float* emb       = (const float*)d_in[3];
    const float* rel_diag  = (const float*)d_in[4];
    const float* rb1       = (const float*)d_in[5];
    const float* rb2       = (const float*)d_in[6];
    const float* bias_head = (const float*)d_in[7];
    const float* bias_tail = (const float*)d_in[8];
    const float* sigma     = (const float*)d_in[9];
    float* out = (float*)d_out;

    prep_kernel<<<TAIL_BLOCKS + HEAD_BLOCKS, 256>>>(
        u_idx, r_idx, emb, rel_diag, rb1, rb2, bias_head, bias_tail, sigma);
    // 1M elements / (4 warps * 32 elem) = 8192 blocks
    score_kernel<<<(BQ * NC) / 128, 128>>>(v_idx, out);
}

// round 12
// speedup vs baseline: 1.3159x; 1.3159x over previous
#include <cuda_runtime.h>
#include <cuda_bf16.h>
#include <cstdint>

// Problem constants (BuseE): N_ENT=200000, N_REL=500, DIM=64, B=1024, NC=1024
#define N_ENT 200000
#define BQ    1024
#define NC    1024
#define MARGIN 9.0f
#define EPS 1e-15f

#define TAIL_BLOCKS (N_ENT / 64)   // 3125 (64 rows / 256-thr block, 4 lanes/row)
#define HEAD_BLOCKS (BQ / 8)       // 128

// ---------------- device scratch (allocation-free) ----------------
// per-entity 128B line: [0,64) = 64 x int8 dims; [64,80) = float4 meta
// meta = { t2, log(max(1-t2,eps)), bias_tail, sc }
__device__ uint4 g_row[N_ENT * 8];          // 25.6 MB
// per-b quantized head: 64 x int8 = 16 words
__device__ unsigned g_headq[BQ * 16];
// per-b: { A, sig, hh, 2*sh/(127*127) }
__device__ float4 g_rowc[BQ];

// ---------------- fast math helpers -------------------------------
__device__ __forceinline__ float tanh_approx(float x) {
    float r;
    asm("tanh.approx.f32 %0, %1;" : "=f"(r) : "f"(x));
    return r;
}

__device__ __forceinline__ float wsum32(float v) {
    #pragma unroll
    for (int m = 16; m; m >>= 1) v += __shfl_xor_sync(0xffffffffu, v, m);
    return v;
}
__device__ __forceinline__ float wmax32(float v) {
    #pragma unroll
    for (int m = 16; m; m >>= 1)
        v = fmaxf(v, __shfl_xor_sync(0xffffffffu, v, m));
    return v;
}

// ---------------- head transform primitives (warp-per-row) --------
__device__ __forceinline__ float2 expmap0_w(float2 v) {
    float n2   = wsum32(v.x * v.x + v.y * v.y);
    float rinv = rsqrtf(fmaxf(n2, 1e-36f));
    float un   = fmaxf(n2 * rinv, EPS);
    float f    = tanh_approx(un) * rinv;
    return make_float2(f * v.x, f * v.y);
}

__device__ __forceinline__ float2 mobius_w(float2 x, float2 y) {
    float x2 = wsum32(x.x * x.x + x.y * x.y);
    float y2 = wsum32(y.x * y.x + y.y * y.y);
    float xy = wsum32(x.x * y.x + x.y * y.y);
    float a   = 1.f + 2.f * xy + y2;
    float bq  = 1.f - x2;
    float inv = 1.f / fmaxf(1.f + 2.f * xy + x2 * y2, EPS);
    return make_float2((a * x.x + bq * y.x) * inv,
                       (a * x.y + bq * y.y) * inv);
}

__device__ __forceinline__ unsigned pack4(float a, float b, float c, float d,
                                          float fi) {
    int q0 = __float2int_rn(a * fi);
    int q1 = __float2int_rn(b * fi);
    int q2 = __float2int_rn(c * fi);
    int q3 = __float2int_rn(d * fi);
    return (q0 & 0xFF) | ((q1 & 0xFF) << 8) | ((q2 & 0xFF) << 16)
         | ((unsigned)(q3 & 0xFF) << 24);
}

// ---------------- fused prep kernel -------------------------------
__global__ void __launch_bounds__(256) prep_kernel(
    const int* __restrict__ u_idx, const int* __restrict__ r_idx,
    const float* __restrict__ emb, const float* __restrict__ rel_diag,
    const float* __restrict__ rb1, const float* __restrict__ rb2,
    const float* __restrict__ bias_head, const float* __restrict__ bias_tail,
    const float* __restrict__ sigma)
{
    if (blockIdx.x < TAIL_BLOCKS) {
        // ---- tail path: 4 lanes per entity row (64 rows / block) ----
        int row = blockIdx.x * 64 + (threadIdx.x >> 2);
        int s   = threadIdx.x & 3;        // lane covers dims [s*16, s*16+16)

        const float4* e4 = reinterpret_cast<const float4*>(emb) + (size_t)row * 16;
        float4 a = e4[s * 4 + 0];
        float4 b = e4[s * 4 + 1];
        float4 c = e4[s * 4 + 2];
        float4 d = e4[s * 4 + 3];

        float p = a.x*a.x + a.y*a.y + a.z*a.z + a.w*a.w
                + b.x*b.x + b.y*b.y + b.z*b.z + b.w*b.w
                + c.x*c.x + c.y*c.y + c.z*c.z + c.w*c.w
                + d.x*d.x + d.y*d.y + d.z*d.z + d.w*d.w;
        float am = fmaxf(fmaxf(fmaxf(fabsf(a.x), fabsf(a.y)),
                               fmaxf(fabsf(a.z), fabsf(a.w))),
                   fmaxf(fmaxf(fabsf(b.x), fabsf(b.y)),
                         fmaxf(fabsf(b.z), fabsf(b.w))));
        am = fmaxf(am, fmaxf(fmaxf(fabsf(c.x), fabsf(c.y)),
                             fmaxf(fabsf(c.z), fabsf(c.w))));
        am = fmaxf(am, fmaxf(fmaxf(fabsf(d.x), fabsf(d.y)),
                             fmaxf(fabsf(d.z), fabsf(d.w))));
        #pragma unroll
        for (int m = 2; m; m >>= 1) {
            p  += __shfl_xor_sync(0xffffffffu, p, m);
            am  = fmaxf(am, __shfl_xor_sync(0xffffffffu, am, m));
        }

        float rinv = rsqrtf(fmaxf(p, 1e-36f));
        float un   = fmaxf(p * rinv, EPS);
        float f    = tanh_approx(un) * rinv;   // tail = f * u
        float sc   = f * am;                   // max |tail_i|
        float fi   = 127.f * f / fmaxf(sc, 1e-30f);

        uint4 o;
        o.x = pack4(a.x, a.y, a.z, a.w, fi);
        o.y = pack4(b.x, b.y, b.z, b.w, fi);
        o.z = pack4(c.x, c.y, c.z, c.w, fi);
        o.w = pack4(d.x, d.y, d.z, d.w, fi);
        g_row[(size_t)row * 8 + s] = o;

        if (s == 0) {
            float t  = tanh_approx(un);
            float t2 = t * t;
            float4 meta = make_float4(t2, __logf(fmaxf(1.f - t2, EPS)),
                                      bias_tail[row], sc);
            g_row[(size_t)row * 8 + 4] = *reinterpret_cast<uint4*>(&meta);
        }
    } else {
        // ---- head path: 1 warp per b-row (8 rows / block) ----
        int b    = (blockIdx.x - TAIL_BLOCKS) * 8 + (threadIdx.x >> 5);
        int lane = threadIdx.x & 31;
        int u = u_idx[b];
        int r = r_idx[b];

        float2 h  = expmap0_w(reinterpret_cast<const float2*>(emb + (size_t)u * 64)[lane]);
        float2 y1 = expmap0_w(reinterpret_cast<const float2*>(rb1 + (size_t)r * 64)[lane]);
        h = mobius_w(h, y1);

        float2 g  = reinterpret_cast<const float2*>(rel_diag + (size_t)r * 64)[lane];
        float gri = rsqrtf(fmaxf(g.x * g.x + g.y * g.y, 1e-36f));
        float gx = g.x * gri, gy = g.y * gri;
        float2 rot = make_float2(gx * h.x - gy * h.y, gy * h.x + gx * h.y);

        float2 y2 = expmap0_w(reinterpret_cast<const float2*>(rb2 + (size_t)r * 64)[lane]);
        h = mobius_w(rot, y2);

        float hh = wsum32(h.x * h.x + h.y * h.y);
        float sh = fmaxf(wmax32(fmaxf(fabsf(h.x), fabsf(h.y))), 1e-30f);
        float inv = 127.f / sh;

        int q0 = __float2int_rn(h.x * inv);
        int q1 = __float2int_rn(h.y * inv);
        unsigned pk = (q0 & 0xFF) | ((q1 & 0xFF) << 8);
        unsigned other = __shfl_xor_sync(0xffffffffu, pk, 1);
        if ((lane & 1) == 0)
            g_headq[b * 16 + (lane >> 1)] = (pk & 0xFFFFu) | (other << 16);

        if (lane == 0) {
            float sg = 1.f / (1.f + __expf(-sigma[r]));
            float A  = MARGIN + bias_head[u]
                     + (1.f - sg) * __logf(fmaxf(1.f - hh, EPS));
            g_rowc[b] = make_float4(A, sg, hh, 2.f * sh / 16129.f);
        }
    }
}

// ---------------- scoring (hot loop) ------------------------------
// Round-10 shape (best measured): warp owns 16 candidates; 8-lane group
// g owns candidates [cbase+4g, +4): idx arrives as ONE int4 LDG.128,
// results leave as ONE float4 STG.128 on the meta lane. Lanes s<4 hold
// int8 dims, lane s==4 holds float4 meta — one 128B line per element.
// ONLY change vs round 10: 32-bit byte offsets into g_row (table is
// 25.6MB) — kills 64-bit IMAD address chains (ALU was top pipe) and
// trims registers for occupancy.
__global__ void __launch_bounds__(128) score_kernel(
    const int* __restrict__ v_idx, float* __restrict__ out)
{
    int w    = threadIdx.x >> 5;
    int gw   = blockIdx.x * 4 + w;       // global warp id
    int b    = gw >> 6;                  // b-row (64 warps per row)
    int seg  = gw & 63;
    int lane = threadIdx.x & 31;
    int g    = lane >> 3;                // group 0..3
    int s    = lane & 7;                 // slot in group

    int cbase = seg * 16;
    const int4* vrow4 = reinterpret_cast<const int4*>(v_idx + b * NC);
    float*      orow  = out + b * NC;

    // head chunk for this slot (s<4 meaningful)
    uint4 hq = reinterpret_cast<const uint4*>(g_headq)[b * 4 + (s & 3)];
    float4 rc = g_rowc[b];               // {A, sig, hh, 2*sh/127^2}

    // ---- one vector idx load: group g's 4 candidates ----
    int4 V = __ldg(vrow4 + seg * 4 + g);
    unsigned off[4] = { (unsigned)V.x * 128u, (unsigned)V.y * 128u,
                        (unsigned)V.z * 128u, (unsigned)V.w * 128u };

    // ---- flat payload gather: 4 lines per group, 32-bit offsets ----
    const char* base = reinterpret_cast<const char*>(g_row);
    unsigned so = (unsigned)s * 16u;
    uint4 p[4];
    #pragma unroll
    for (int j = 0; j < 4; j++) {
        p[j] = make_uint4(0u, 0u, 0u, 0u);
        if (s < 5)
            p[j] = *reinterpret_cast<const uint4*>(base + (off[j] + so));
    }

    // ---- integer dot ----
    int I[4];
    #pragma unroll
    for (int j = 0; j < 4; j++) {
        int acc = 0;
        if (s < 4) {
            acc = __dp4a((int)p[j].x, (int)hq.x, acc);
            acc = __dp4a((int)p[j].y, (int)hq.y, acc);
            acc = __dp4a((int)p[j].z, (int)hq.z, acc);
            acc = __dp4a((int)p[j].w, (int)hq.w, acc);
        }
        I[j] = acc;
    }

    #pragma unroll
    for (int m = 1; m <= 4; m <<= 1) {
        #pragma unroll
        for (int j = 0; j < 4; j++)
            I[j] += __shfl_xor_sync(0xffffffffu, I[j], m);
    }

    // ---- epilogue + one STG.128 on meta lane ----
    if (s == 4) {
        float res[4];
        #pragma unroll
        for (int j = 0; j < 4; j++) {
            float4 mt = *reinterpret_cast<float4*>(&p[j]);  // {t2,l,bias,sc}
            float K   = rc.w * mt.w;
            float num = fmaxf(rc.z + mt.x - K * (float)I[j], EPS);
            res[j]    = rc.x + fmaf(rc.y, mt.y, mt.z) - __logf(num);
        }
        *reinterpret_cast<float4*>(orow + cbase + 4 * g) =
            make_float4(res[0], res[1], res[2], res[3]);
    }
}

// ---------------- launch ------------------------------------------
extern "C" void kernel_launch(void* const* d_in, const int* in_sizes, int n_in,
                              void* d_out, int out_size)
{
    const int*   u_idx     = (const int*)  d_in[0];
    const int*   r_idx     = (const int*)  d_in[1];
    const int*   v_idx     = (const int*)  d_in[2];
    const float* emb       = (const float*)d_in[3];
    const float* rel_diag  = (const float*)d_in[4];
    const float* rb1       = (const float*)d_in[5];
    const float* rb2       = (const float*)d_in[6];
    const float* bias_head = (const float*)d_in[7];
    const float* bias_tail = (const float*)d_in[8];
    const float* sigma     = (const float*)d_in[9];
    float* out = (float*)d_out;

    prep_kernel<<<TAIL_BLOCKS + HEAD_BLOCKS, 256>>>(
        u_idx, r_idx, emb, rel_diag, rb1, rb2, bias_head, bias_tail, sigma);
    // 1M elements / (4 warps * 16 elem) = 16384 blocks
    score_kernel<<<(BQ * NC) / 64, 128>>>(v_idx, out);
}